// round 16
// baseline (speedup 1.0000x reference)
#include <cuda_runtime.h>
#include <cstdint>
#include <math.h>

#define EMB   1024
#define NH    16
#define HD    64
#define INNER 1024
#define BATCH 2
#define SEQ   2048
#define MROWS (BATCH*SEQ)   // 4096

// Scratch (allocation-free rule: device globals)
__device__ float g_q[(size_t)MROWS*INNER];
__device__ float g_k[(size_t)MROWS*INNER];
__device__ float g_v[(size_t)MROWS*INNER];
__device__ float g_att[(size_t)MROWS*INNER];

__device__ __forceinline__ uint32_t f2tf32(float x) {
    uint32_t r;
    asm("cvt.rna.tf32.f32 %0, %1;" : "=r"(r) : "f"(x));
    return r;
}

#define MMA_TF32(c, a0,a1,a2,a3, b0,b1)                                        \
    asm volatile(                                                              \
        "mma.sync.aligned.m16n8k8.row.col.f32.tf32.tf32.f32 "                  \
        "{%0,%1,%2,%3}, {%4,%5,%6,%7}, {%8,%9}, {%0,%1,%2,%3};"                \
        : "+f"((c)[0]), "+f"((c)[1]), "+f"((c)[2]), "+f"((c)[3])               \
        : "r"(a0), "r"(a1), "r"(a2), "r"(a3), "r"(b0), "r"(b1))

// ---------------------------------------------------------------------------
// TF32 mma.sync GEMM, fragment-major smem + double buffer, 2 CTAs/SM.
// C[m][n] = sum_k A[m][k]*W[n][k] (+bias[n]).  CTA 128x128, K-chunk 32.
// 8 warps (4m x 2n), warp tile 32x64.  No register staging (regs <= 128);
// latency hidden by the co-resident CTA.
// ---------------------------------------------------------------------------
#define APITCH 132
#define BPITCH 66
#define ABUF (32*APITCH)                 // 4224 words
#define BBUF (64*BPITCH)                 // 4224 words
#define GEMM_SMEM_WORDS (2*ABUF + 2*BBUF)
#define GEMM_SMEM_BYTES (GEMM_SMEM_WORDS*4)   // 67584

template<bool BIAS>
__device__ __forceinline__ void gemm_core(
    const float* __restrict__ A, const float* __restrict__ W,
    const float* __restrict__ bias, float* __restrict__ C,
    const int bm, const int bn)
{
    extern __shared__ uint32_t sm[];
    uint32_t* const SA0 = sm;
    uint32_t* const SA1 = sm + ABUF;
    uint32_t* const SB0 = sm + 2*ABUF;
    uint32_t* const SB1 = sm + 2*ABUF + BBUF;

    const int tid  = threadIdx.x;
    const int wid  = tid >> 5;
    const int lane = tid & 31;
    const int g    = lane >> 2;
    const int t4   = lane & 3;
    const int mg0  = (wid & 3) * 2;      // A 16-row block base
    const int ng0  = (wid >> 2) * 8;     // B 8-row block base
    const int K    = 1024;

    const int lrow  = tid >> 3;          // 0..31
    const int lc4   = tid & 7;           // float4 index in 32-col chunk
    const int ks_st = lc4 >> 1;
    const int wA    = (lc4 & 1) * 2;
    const int wB    = lc4 & 1;

    float c[2][8][4];
    #pragma unroll
    for (int mt = 0; mt < 2; mt++)
        #pragma unroll
        for (int nt = 0; nt < 8; nt++)
            #pragma unroll
            for (int i = 0; i < 4; i++) c[mt][nt][i] = 0.f;

    for (int ch = 0; ch < 32; ch++) {
        const int p = ch & 1;
        uint32_t* da = p ? SA1 : SA0;
        uint32_t* db = p ? SB1 : SB0;
        const int k0 = ch * 32;
        #pragma unroll
        for (int i = 0; i < 4; i++) {
            int row = lrow + i * 32;
            float4 av = *(const float4*)(A + (size_t)(bm + row) * K + k0 + lc4 * 4);
            float4 bv = *(const float4*)(W + (size_t)(bn + row) * K + k0 + lc4 * 4);
            int mg = row >> 4, lr = row & 15, hw = lr >> 3, ga = lr & 7;
            uint32_t ab = (mg * 4 + ks_st) * APITCH + ga * 16 + wA + hw;
            da[ab+0]  = f2tf32(av.x); da[ab+4]  = f2tf32(av.y);
            da[ab+8]  = f2tf32(av.z); da[ab+12] = f2tf32(av.w);
            int ng = row >> 3, gb = row & 7;
            uint32_t bb = (ng * 4 + ks_st) * BPITCH + gb * 8 + wB;
            db[bb+0] = f2tf32(bv.x); db[bb+2] = f2tf32(bv.y);
            db[bb+4] = f2tf32(bv.z); db[bb+6] = f2tf32(bv.w);
        }
        __syncthreads();

        const uint32_t* sa = da;
        const uint32_t* sb = db;
        #pragma unroll
        for (int ks = 0; ks < 4; ks++) {
            uint4 a0 = *(const uint4*)&sa[((mg0    ) * 4 + ks) * APITCH + (g*4 + t4) * 4];
            uint4 a1 = *(const uint4*)&sa[((mg0 + 1) * 4 + ks) * APITCH + (g*4 + t4) * 4];
            #pragma unroll
            for (int nt = 0; nt < 8; nt++) {
                uint2 b = *(const uint2*)&sb[((ng0 + nt) * 4 + ks) * BPITCH + (g*4 + t4) * 2];
                MMA_TF32(c[0][nt], a0.x, a0.y, a0.z, a0.w, b.x, b.y);
                MMA_TF32(c[1][nt], a1.x, a1.y, a1.z, a1.w, b.x, b.y);
            }
        }
        // no trailing sync: next chunk writes the other buffer; reuse of this
        // buffer (ch+2) is fenced by the sync inside chunk ch+1.
    }

    // ---- epilogue ----
    const int wm = (wid & 3) * 32;
    const int wn = (wid >> 2) * 64;
    #pragma unroll
    for (int mt = 0; mt < 2; mt++) {
        #pragma unroll
        for (int nt = 0; nt < 8; nt++) {
            const int col = bn + wn + nt * 8 + 2 * t4;
            float bx = 0.f, by = 0.f;
            if (BIAS) { bx = bias[col]; by = bias[col + 1]; }
            const int r0 = bm + wm + mt * 16 + g;
            float2 v0 = make_float2(c[mt][nt][0] + bx, c[mt][nt][1] + by);
            float2 v1 = make_float2(c[mt][nt][2] + bx, c[mt][nt][3] + by);
            *(float2*)(C + (size_t)r0 * 1024 + col)       = v0;
            *(float2*)(C + (size_t)(r0 + 8) * 1024 + col) = v1;
        }
    }
}

__global__ __launch_bounds__(256, 2) void gemm_qkv(
    const float* __restrict__ q, const float* __restrict__ k,
    const float* __restrict__ v,
    const float* __restrict__ Wq, const float* __restrict__ Wk,
    const float* __restrict__ Wv,
    float* __restrict__ oq, float* __restrict__ ok, float* __restrict__ ov)
{
    const float* A; const float* W; float* C;
    if (blockIdx.z == 0)      { A = q; W = Wq; C = oq; }
    else if (blockIdx.z == 1) { A = k; W = Wk; C = ok; }
    else                      { A = v; W = Wv; C = ov; }
    gemm_core<false>(A, W, nullptr, C, blockIdx.y * 128, blockIdx.x * 128);
}

__global__ __launch_bounds__(256, 2) void gemm_out(
    const float* __restrict__ A, const float* __restrict__ W,
    const float* __restrict__ bias, float* __restrict__ C)
{
    gemm_core<true>(A, W, bias, C, blockIdx.y * 128, blockIdx.x * 128);
}

// ---------------------------------------------------------------------------
// Tensor-core flash attention (tf32 mma.sync), 256 threads / 128 queries.
// 8 warps x 16 query rows; KV tiles of 64 keys, register-staged prefetch.
// Smem words: Ks[64][68] @0, Vs[64][72], QP[128][68], pms[64].
// ---------------------------------------------------------------------------
#define KP 68
#define VP 72
#define ATT_SMEM_WORDS (64*KP + 64*VP + 128*KP + 64)
#define ATT_SMEM_BYTES (ATT_SMEM_WORDS*4)     // 70912

__global__ __launch_bounds__(256) void attn_mma(
    const float* __restrict__ Q, const float* __restrict__ K,
    const float* __restrict__ V, const int* __restrict__ pmask,
    const int* __restrict__ fmask, float* __restrict__ O)
{
    extern __shared__ uint32_t dsm[];
    uint32_t* Ks  = dsm;                         // [64][KP]
    uint32_t* Vs  = dsm + 64*KP;                 // [64][VP]
    uint32_t* QP  = dsm + 64*KP + 64*VP;         // [128][KP]  Q staging, then P
    int*      pms = (int*)(dsm + 64*KP + 64*VP + 128*KP);

    const int b  = blockIdx.z;
    const int h  = blockIdx.y;
    const int q0 = SEQ - 128 - blockIdx.x * 128;   // heavy CTAs first
    const int tid  = threadIdx.x;
    const int w    = tid >> 5;
    const int lane = tid & 31;
    const int g    = lane >> 2;
    const int t4   = lane & 3;

    const bool causal = (*fmask != 0);
    const int* pm = pmask + (size_t)b * SEQ;

    // ---- stage Q (scaled, tf32) ----
    {
        const float scale = 0.125f;
        #pragma unroll
        for (int i = tid; i < 128 * 16; i += 256) {
            int row = i >> 4;
            int c4  = i & 15;
            float4 t = *(const float4*)(Q + (size_t)(b*SEQ + q0 + row) * INNER + h*HD + c4*4);
            uint32_t* p = QP + row * KP + c4 * 4;
            p[0] = f2tf32(t.x * scale); p[1] = f2tf32(t.y * scale);
            p[2] = f2tf32(t.z * scale); p[3] = f2tf32(t.w * scale);
        }
    }
    __syncthreads();

    // ---- Q fragments (A operand), register resident ----
    uint32_t qf[8][4];
    #pragma unroll
    for (int kt = 0; kt < 8; kt++) {
        const uint32_t* base = QP + (w*16 + g) * KP + kt*8 + t4;
        qf[kt][0] = base[0];
        qf[kt][1] = base[8*KP];
        qf[kt][2] = base[4];
        qf[kt][3] = base[8*KP + 4];
    }

    float o[8][4];
    #pragma unroll
    for (int nt = 0; nt < 8; nt++)
        #pragma unroll
        for (int i = 0; i < 4; i++) o[nt][i] = 0.f;

    float m0 = -INFINITY, m1 = -INFINITY, l0 = 0.f, l1 = 0.f;
    const int r0    = q0 + w*16 + g;       // global query row (and r0+8)
    const int rlo   = q0 + w*16;           // warp's lowest row
    const int wlim  = rlo + 15;            // warp's highest row

    const int ntiles = causal ? (q0/64 + 2) : (SEQ/64);

    // KV staging: 64 rows x 16 float4 per matrix / 256 threads = 4 each
    const int srow = tid >> 2;             // 0..63
    const int sc4  = tid & 3;              // x4 -> 16 float4/row
    float4 kst[4], vst[4];
    int pmv = 0;

    // prologue: stage tile 0
    {
        #pragma unroll
        for (int ii = 0; ii < 4; ii++) {
            const size_t goff = (size_t)(b*SEQ + srow) * INNER + h*HD + (sc4 + ii*4)*4;
            kst[ii] = *(const float4*)(K + goff);
            vst[ii] = *(const float4*)(V + goff);
        }
        if (tid < 64) pmv = pm[tid];
    }

    for (int tile = 0; tile < ntiles; tile++) {
        const int j0 = tile * 64;
        __syncthreads();   // previous tile's smem reads complete (t=0: after Q staging reads)

        // ---- STS staged KV (tf32) ----
        #pragma unroll
        for (int ii = 0; ii < 4; ii++) {
            uint32_t* kp = Ks + srow * KP + (sc4 + ii*4) * 4;
            uint32_t* vp = Vs + srow * VP + (sc4 + ii*4) * 4;
            kp[0] = f2tf32(kst[ii].x); kp[1] = f2tf32(kst[ii].y);
            kp[2] = f2tf32(kst[ii].z); kp[3] = f2tf32(kst[ii].w);
            vp[0] = f2tf32(vst[ii].x); vp[1] = f2tf32(vst[ii].y);
            vp[2] = f2tf32(vst[ii].z); vp[3] = f2tf32(vst[ii].w);
        }
        if (tid < 64) pms[tid] = pmv;
        __syncthreads();

        // ---- prefetch next tile into regs (hidden behind compute) ----
        if (tile + 1 < ntiles) {
            const int jn = j0 + 64;
            #pragma unroll
            for (int ii = 0; ii < 4; ii++) {
                const size_t goff = (size_t)(b*SEQ + jn + srow) * INNER + h*HD + (sc4 + ii*4)*4;
                kst[ii] = *(const float4*)(K + goff);
                vst[ii] = *(const float4*)(V + goff);
            }
            if (tid < 64) pmv = pm[jn + tid];
        }

        // warps entirely above the diagonal skip the compute (barriers stay uniform)
        if (causal && j0 > wlim) continue;

        // ---- S = Q @ K^T ----
        float s[8][4];
        #pragma unroll
        for (int nt = 0; nt < 8; nt++)
            #pragma unroll
            for (int i = 0; i < 4; i++) s[nt][i] = 0.f;

        #pragma unroll
        for (int kt = 0; kt < 8; kt++) {
            #pragma unroll
            for (int nt = 0; nt < 8; nt++) {
                const uint32_t* bb = Ks + (nt*8 + g) * KP + kt*8 + t4;
                uint32_t b0 = bb[0];
                uint32_t b1 = bb[4];
                MMA_TF32(s[nt], qf[kt][0], qf[kt][1], qf[kt][2], qf[kt][3], b0, b1);
            }
        }

        // ---- mask ----
        const bool diag = causal && (j0 + 63 > rlo);
        #pragma unroll
        for (int nt = 0; nt < 8; nt++) {
            const int c0 = nt*8 + 2*t4;
            const int c1 = c0 + 1;
            const bool p0 = (pms[c0] != 0);
            const bool p1 = (pms[c1] != 0);
            if (!p0 || (diag && j0 + c0 > r0))     s[nt][0] = -INFINITY;
            if (!p1 || (diag && j0 + c1 > r0))     s[nt][1] = -INFINITY;
            if (!p0 || (diag && j0 + c0 > r0 + 8)) s[nt][2] = -INFINITY;
            if (!p1 || (diag && j0 + c1 > r0 + 8)) s[nt][3] = -INFINITY;
        }

        // ---- online softmax ----
        float t0 = -INFINITY, t1 = -INFINITY;
        #pragma unroll
        for (int nt = 0; nt < 8; nt++) {
            t0 = fmaxf(t0, fmaxf(s[nt][0], s[nt][1]));
            t1 = fmaxf(t1, fmaxf(s[nt][2], s[nt][3]));
        }
        t0 = fmaxf(t0, __shfl_xor_sync(0xFFFFFFFFu, t0, 1));
        t0 = fmaxf(t0, __shfl_xor_sync(0xFFFFFFFFu, t0, 2));
        t1 = fmaxf(t1, __shfl_xor_sync(0xFFFFFFFFu, t1, 1));
        t1 = fmaxf(t1, __shfl_xor_sync(0xFFFFFFFFu, t1, 2));

        const float mn0 = fmaxf(m0, t0);
        const float mn1 = fmaxf(m1, t1);
        const float corr0 = __expf(m0 - mn0);
        const float corr1 = __expf(m1 - mn1);
        m0 = mn0; m1 = mn1;

        float sum0 = 0.f, sum1 = 0.f;
        #pragma unroll
        for (int nt = 0; nt < 8; nt++) {
            s[nt][0] = __expf(s[nt][0] - mn0); sum0 += s[nt][0];
            s[nt][1] = __expf(s[nt][1] - mn0); sum0 += s[nt][1];
            s[nt][2] = __expf(s[nt][2] - mn1); sum1 += s[nt][2];
            s[nt][3] = __expf(s[nt][3] - mn1); sum1 += s[nt][3];
        }
        sum0 += __shfl_xor_sync(0xFFFFFFFFu, sum0, 1);
        sum0 += __shfl_xor_sync(0xFFFFFFFFu, sum0, 2);
        sum1 += __shfl_xor_sync(0xFFFFFFFFu, sum1, 1);
        sum1 += __shfl_xor_sync(0xFFFFFFFFu, sum1, 2);
        l0 = l0 * corr0 + sum0;
        l1 = l1 * corr1 + sum1;

        // ---- P -> warp-private smem (tf32), reload as A fragments ----
        uint32_t* Ps = QP + w * 16 * KP;
        #pragma unroll
        for (int nt = 0; nt < 8; nt++) {
            const int c0 = nt*8 + 2*t4;
            Ps[g*KP + c0]           = f2tf32(s[nt][0]);
            Ps[g*KP + c0 + 1]       = f2tf32(s[nt][1]);
            Ps[(g+8)*KP + c0]       = f2tf32(s[nt][2]);
            Ps[(g+8)*KP + c0 + 1]   = f2tf32(s[nt][3]);
        }
        __syncwarp();

        #pragma unroll
        for (int nt = 0; nt < 8; nt++) {
            o[nt][0] *= corr0; o[nt][1] *= corr0;
            o[nt][2] *= corr1; o[nt][3] *= corr1;
        }

        // ---- O += P @ V ----
        #pragma unroll
        for (int kt = 0; kt < 8; kt++) {
            uint32_t a0 = Ps[g*KP + kt*8 + t4];
            uint32_t a1 = Ps[(g+8)*KP + kt*8 + t4];
            uint32_t a2 = Ps[g*KP + kt*8 + t4 + 4];
            uint32_t a3 = Ps[(g+8)*KP + kt*8 + t4 + 4];
            #pragma unroll
            for (int nt = 0; nt < 8; nt++) {
                uint32_t b0 = Vs[(kt*8 + t4)     * VP + nt*8 + g];
                uint32_t b1 = Vs[(kt*8 + t4 + 4) * VP + nt*8 + g];
                MMA_TF32(o[nt], a0, a1, a2, a3, b0, b1);
            }
        }
    }

    // ---- epilogue ----
    const float inv0 = 1.f / l0;
    const float inv1 = 1.f / l1;
    float* op0 = O + (size_t)(b*SEQ + r0)     * INNER + h*HD;
    float* op1 = O + (size_t)(b*SEQ + r0 + 8) * INNER + h*HD;
    #pragma unroll
    for (int nt = 0; nt < 8; nt++) {
        const int col = nt*8 + 2*t4;
        *(float2*)(op0 + col) = make_float2(o[nt][0]*inv0, o[nt][1]*inv0);
        *(float2*)(op1 + col) = make_float2(o[nt][2]*inv1, o[nt][3]*inv1);
    }
}

// ---------------------------------------------------------------------------
extern "C" void kernel_launch(void* const* d_in, const int* in_sizes, int n_in,
                              void* d_out, int out_size)
{
    const float* query = (const float*)d_in[0];
    const float* key   = (const float*)d_in[1];
    const float* value = (const float*)d_in[2];
    const int*   pmask = (const int*)d_in[3];
    const int*   fmask = (const int*)d_in[4];
    const float* Wq = (const float*)d_in[5];
    const float* Wk = (const float*)d_in[6];
    const float* Wv = (const float*)d_in[7];
    const float* Wo = (const float*)d_in[8];
    const float* bo = (const float*)d_in[9];
    float* out = (float*)d_out;

    float *gq, *gk, *gv, *gatt;
    cudaGetSymbolAddress((void**)&gq,   g_q);
    cudaGetSymbolAddress((void**)&gk,   g_k);
    cudaGetSymbolAddress((void**)&gv,   g_v);
    cudaGetSymbolAddress((void**)&gatt, g_att);

    cudaFuncSetAttribute(gemm_qkv,
                         cudaFuncAttributeMaxDynamicSharedMemorySize, GEMM_SMEM_BYTES);
    cudaFuncSetAttribute(gemm_out,
                         cudaFuncAttributeMaxDynamicSharedMemorySize, GEMM_SMEM_BYTES);
    cudaFuncSetAttribute(attn_mma,
                         cudaFuncAttributeMaxDynamicSharedMemorySize, ATT_SMEM_BYTES);

    dim3 qkvgrid(INNER/128, MROWS/128, 3);  // (8, 32, 3)
    gemm_qkv<<<qkvgrid, 256, GEMM_SMEM_BYTES>>>(query, key, value,
                                                Wq, Wk, Wv, gq, gk, gv);

    dim3 agrid(SEQ/128, NH, BATCH);         // (16, 16, 2)
    attn_mma<<<agrid, 256, ATT_SMEM_BYTES>>>(gq, gk, gv, pmask, fmask, gatt);

    dim3 ogrid(EMB/128, MROWS/128);         // (8, 32)
    gemm_out<<<ogrid, 256, GEMM_SMEM_BYTES>>>(gatt, Wo, bo, out);
}